// round 11
// baseline (speedup 1.0000x reference)
#include <cuda_runtime.h>
#include <math.h>

#define NUM_USERS 100000
#define NUM_ITEMS 50000
#define NROWS     150000      // NUM_USERS + NUM_ITEMS
#define NPAD      150016      // padded row count
#define EMB       64
#define NEDGES    2400000
#define NLAYERS   3
#define NEG_SLOPE 0.01f

#define SCAN_CHUNK 2048
#define NUM_CHUNKS ((NROWS + SCAN_CHUNK - 1) / SCAN_CHUNK)   // 74
#define NTILES    ((NROWS + 63) / 64)                        // 2344
#define TR_GRID   444                                        // 148 SM x 3 blocks

typedef unsigned long long u64;

// packed fp32x2 FMA (Blackwell; ptxas never auto-fuses -> inline PTX)
#define FMA2(d, a, b, c) \
    asm("fma.rn.f32x2 %0, %1, %2, %3;" : "=l"(d) : "l"(a), "l"(b), "l"(c))
#define PACK2(d, lo, hi) \
    asm("mov.b64 %0, {%1, %2};" : "=l"(d) : "f"(lo), "f"(hi))
#define UNPACK2(lo, hi, v) \
    asm("mov.b64 {%0, %1}, %2;" : "=f"(lo), "=f"(hi) : "l"(v))

// -------- persistent device scratch (no allocations allowed) --------
__device__ __align__(16) float g_ego [NPAD * EMB];
__device__ __align__(16) float g_side[NPAD * EMB];
__device__ int  g_row_ptr[NROWS + 1];
__device__ int  g_cursor [NROWS];        // zeroed by transform(layer 0) for next replay
__device__ __align__(16) int2 g_edge[NEDGES];  // (col, val-bits)
// decoupled-lookback scan state + per-chunk done flags; zeroed by k_spmm.
__device__ volatile u64 g_scan_state[NUM_CHUNKS];
__device__ unsigned g_chunk_done[NUM_CHUNKS];

// ---------------------------------------------------------------
// Launch 0: hist (atomics into cursor) + ego init + out layer-0.
// ---------------------------------------------------------------
__global__ void k_hist_init(const int* __restrict__ rows,
                            const float* __restrict__ user_emb,
                            const float* __restrict__ item_emb,
                            float* __restrict__ out, int n_edges) {
    int idx = blockIdx.x * blockDim.x + threadIdx.x;
    if (idx < n_edges) atomicAdd(&g_cursor[rows[idx]], 1);
    if (idx >= NROWS * 16) return;
    int r = idx >> 4;
    int c4 = idx & 15;
    float4 v;
    if (r < NUM_USERS)
        v = ((const float4*)&user_emb[r * EMB])[c4];
    else
        v = ((const float4*)&item_emb[(r - NUM_USERS) * EMB])[c4];
    ((float4*)&g_ego[r * EMB])[c4] = v;
    ((float4*)&out[r * (EMB * (NLAYERS + 1))])[c4] = v;
}

// ---------------------------------------------------------------
// Launch 1: fused scan (blocks 0..73) + scatter (all blocks).
// Scan blocks are lowest bids -> wave-1 resident -> no deadlock.
// ---------------------------------------------------------------
__global__ void __launch_bounds__(256)
k_scan_scatter(const int* __restrict__ rows,
               const int* __restrict__ cols,
               const float* __restrict__ vals, int n_edges) {
    int b = blockIdx.x, t = threadIdx.x;

    if (b < NUM_CHUNKS) {
        // ---- scan for chunk b ----
        int base = b * SCAN_CHUNK + t * 8;
        int v[8];
        int local = 0;
#pragma unroll
        for (int i = 0; i < 8; i++) {
            int idx = base + i;
            v[i] = (idx < NROWS) ? g_cursor[idx] : 0;
            local += v[i];
        }
        __shared__ int sh[256];
        __shared__ int s_prev;
        sh[t] = local;
        __syncthreads();
        for (int d = 1; d < 256; d <<= 1) {
            int x = (t >= d) ? sh[t - d] : 0;
            __syncthreads();
            sh[t] += x;
            __syncthreads();
        }
        if (t == 255) {
            u64 agg = (u64)(unsigned)sh[255];
            if (b == 0) {
                g_scan_state[0] = (2ull << 62) | agg;
                s_prev = 0;
            } else {
                g_scan_state[b] = (1ull << 62) | agg;
                int prev = 0;
                int j = b - 1;
                while (j >= 0) {
                    u64 st;
                    do { st = g_scan_state[j]; } while ((st >> 62) == 0);
                    if ((st >> 62) == 2ull) { prev += (int)(unsigned)st; break; }
                    prev += (int)(unsigned)st;
                    j--;
                }
                g_scan_state[b] = (2ull << 62) | (u64)(unsigned)(prev + sh[255]);
                s_prev = prev;
            }
        }
        __syncthreads();

        int exc = s_prev + (t ? sh[t - 1] : 0);
#pragma unroll
        for (int i = 0; i < 8; i++) {
            int idx = base + i;
            if (idx < NROWS) {
                g_row_ptr[idx] = exc;
                g_cursor[idx]  = exc;
            }
            exc += v[i];
        }
        if (b == NUM_CHUNKS - 1 && t == 255)
            g_row_ptr[NROWS] = s_prev + sh[255];

        __syncthreads();
        __threadfence();
        if (t == 0)
            asm volatile("st.global.release.gpu.u32 [%0], %1;"
                         :: "l"(&g_chunk_done[b]), "r"(1u) : "memory");
    }

    // ---- scatter (all blocks) ----
    int e = b * 256 + t;
    if (e < n_edges) {
        int r = rows[e];
        int c = r >> 11;                  // chunk index (SCAN_CHUNK = 2048)
        unsigned done;
        do {
            asm volatile("ld.global.acquire.gpu.u32 %0, [%1];"
                         : "=r"(done) : "l"(&g_chunk_done[c]) : "memory");
            if (!done) __nanosleep(64);
        } while (!done);
        int pos = atomicAdd(&g_cursor[r], 1);
        g_edge[pos] = make_int2(cols[e], __float_as_int(vals[e]));
    }
}

// ---------------------------------------------------------------
// Launch 2: SpMM side = A @ ego, warp per row; also clears scan flags.
// ---------------------------------------------------------------
__global__ void k_spmm() {
    int gid = blockIdx.x * blockDim.x + threadIdx.x;
    if (gid < NUM_CHUNKS) { g_scan_state[gid] = 0; g_chunk_done[gid] = 0; }
    int w = gid >> 5;
    int lane = threadIdx.x & 31;
    if (w >= NROWS) return;
    int s = g_row_ptr[w];
    int e = g_row_ptr[w + 1];
    float2 acc = make_float2(0.f, 0.f);
    for (int i = s; i < e; i++) {
        int2 ed = __ldg(&g_edge[i]);
        float v = __int_as_float(ed.y);
        float2 x = *(const float2*)&g_ego[ed.x * EMB + lane * 2];
        acc.x = fmaf(v, x.x, acc.x);
        acc.y = fmaf(v, x.y, acc.y);
    }
    *(float2*)&g_side[w * EMB + lane * 2] = acc;
}

// ---------------------------------------------------------------
// Launch 3 (PROFILED): transform, persistent blocks, W loaded once.
// 64-row tiles, 256 threads, thread computes 16 cols of one row.
// ---------------------------------------------------------------
__device__ __forceinline__ float lrelu(float a) {
    return (a > 0.f) ? a : NEG_SLOPE * a;
}

__global__ void __launch_bounds__(256)
k_transform(const float* __restrict__ W1g, const float* __restrict__ b1g,
            const float* __restrict__ W2g, const float* __restrict__ b2g,
            float* __restrict__ out, int layer) {
    extern __shared__ float sh[];
    float* W1s   = sh;                 // 4096
    float* W2s   = sh + 4096;          // 4096
    float* b1s   = sh + 8192;          // 64
    float* b2s   = sh + 8256;          // 64
    float* ssq   = sh + 8320;          // 256
    float* sideS = sh + 8576;          // 64*65 = 4160
    float* uS    = sideS + 4160;       // 4160
    // total = 16896 floats = 67584 bytes -> 3 blocks/SM

    int t = threadIdx.x;

    // load weights ONCE per block
#pragma unroll 4
    for (int i = t; i < 1024; i += 256) {
        ((float4*)W1s)[i] = ((const float4*)W1g)[i];
        ((float4*)W2s)[i] = ((const float4*)W2g)[i];
    }
    if (t < 64) { b1s[t] = b1g[t]; b2s[t] = b2g[t]; }

    int row = t & 63;         // row within tile
    int q   = t >> 6;         // col quarter: cols q*16 .. q*16+15

    for (int tile = blockIdx.x; tile < NTILES; tile += TR_GRID) {
        int base = tile * 64;
        __syncthreads();      // smem safe to overwrite (also orders W on iter 0)

        // stage side + u = ego*side for this tile (padded stride 65)
        const float4* sg = (const float4*)&g_side[(size_t)base * EMB];
        const float4* eg = (const float4*)&g_ego [(size_t)base * EMB];
#pragma unroll 4
        for (int i = t; i < 1024; i += 256) {
            float4 sv = sg[i];
            float4 ev = eg[i];
            int rw = i >> 4;
            int c = (i & 15) * 4;
            float* ds = &sideS[rw * 65 + c];
            float* du = &uS   [rw * 65 + c];
            ds[0] = sv.x; ds[1] = sv.y; ds[2] = sv.z; ds[3] = sv.w;
            du[0] = ev.x * sv.x; du[1] = ev.y * sv.y;
            du[2] = ev.z * sv.z; du[3] = ev.w * sv.w;
        }
        __syncthreads();

        int r = base + row;

        // re-zero histogram counters for next replay (cursor dead by now)
        if (layer == 0 && q == 0 && r < NROWS) g_cursor[r] = 0;

        float o[16];

        if (r < NROWS) {
            const float* srow = &sideS[row * 65];
            const float* urow = &uS[row * 65];

            u64 acc1[8], acc2[8];
#pragma unroll
            for (int j = 0; j < 8; j++) {
                PACK2(acc1[j], b1s[q * 16 + 2 * j], b1s[q * 16 + 2 * j + 1]);
                PACK2(acc2[j], b2s[q * 16 + 2 * j], b2s[q * 16 + 2 * j + 1]);
            }
#pragma unroll 4
            for (int k = 0; k < 64; k++) {
                float s = srow[k];
                float u = urow[k];
                u64 ss, uu;
                PACK2(ss, s, s);
                PACK2(uu, u, u);
                const u64* w1 = (const u64*)&W1s[k * 64 + q * 16];
                const u64* w2 = (const u64*)&W2s[k * 64 + q * 16];
#pragma unroll
                for (int j = 0; j < 8; j += 2) {
                    ulonglong2 a = *(const ulonglong2*)&w1[j];
                    FMA2(acc1[j],     ss, a.x, acc1[j]);
                    FMA2(acc1[j + 1], ss, a.y, acc1[j + 1]);
                    ulonglong2 b = *(const ulonglong2*)&w2[j];
                    FMA2(acc2[j],     uu, b.x, acc2[j]);
                    FMA2(acc2[j + 1], uu, b.y, acc2[j + 1]);
                }
            }

            float sumsq = 0.f;
#pragma unroll
            for (int j = 0; j < 8; j++) {
                float a0, a1, b0, b1;
                UNPACK2(a0, a1, acc1[j]);
                UNPACK2(b0, b1, acc2[j]);
                float o0 = lrelu(a0) + lrelu(b0);
                float o1 = lrelu(a1) + lrelu(b1);
                sumsq += o0 * o0 + o1 * o1;
                o[2 * j]     = o0;
                o[2 * j + 1] = o1;
            }
            ssq[t] = sumsq;   // t = q*64 + row

            float4* egor = (float4*)&g_ego[(size_t)r * EMB + q * 16];
#pragma unroll
            for (int j4 = 0; j4 < 4; j4++)
                egor[j4] = make_float4(o[j4 * 4], o[j4 * 4 + 1],
                                       o[j4 * 4 + 2], o[j4 * 4 + 3]);
        }
        __syncthreads();

        if (r < NROWS) {
            float total = ssq[row] + ssq[64 + row] + ssq[128 + row] + ssq[192 + row];
            float inv = 1.0f / fmaxf(sqrtf(total), 1e-12f);
            float4* orow = (float4*)&out[(size_t)r * (EMB * (NLAYERS + 1))
                                         + (layer + 1) * EMB + q * 16];
#pragma unroll
            for (int j4 = 0; j4 < 4; j4++)
                orow[j4] = make_float4(o[j4 * 4] * inv, o[j4 * 4 + 1] * inv,
                                       o[j4 * 4 + 2] * inv, o[j4 * 4 + 3] * inv);
        }
    }
}

// ---------------------------------------------------------------
extern "C" void kernel_launch(void* const* d_in, const int* in_sizes, int n_in,
                              void* d_out, int out_size) {
    const int*   adj_rows = (const int*)  d_in[0];
    const int*   adj_cols = (const int*)  d_in[1];
    const float* adj_vals = (const float*)d_in[2];
    const float* user_emb = (const float*)d_in[3];
    const float* item_emb = (const float*)d_in[4];
    const float* gc_w     = (const float*)d_in[5];
    const float* gc_b     = (const float*)d_in[6];
    const float* bi_w     = (const float*)d_in[7];
    const float* bi_b     = (const float*)d_in[8];
    float*       out      = (float*)d_out;

    int n_edges = in_sizes[0];

    const int smem_bytes = 16896 * (int)sizeof(float); // 67584
    cudaFuncSetAttribute(k_transform, cudaFuncAttributeMaxDynamicSharedMemorySize, smem_bytes);

    // launch 0: hist + ego init + layer-0 out
    k_hist_init<<<(n_edges + 255) / 256, 256>>>(adj_rows, user_emb, item_emb,
                                                out, n_edges);
    // launch 1: fused scan + scatter
    k_scan_scatter<<<(n_edges + 255) / 256, 256>>>(adj_rows, adj_cols, adj_vals,
                                                   n_edges);

    // launches 2..7: layers (transform at index 3 -> profiled)
    int spmm_blocks = (NROWS * 32 + 255) / 256;        // warp per row
    for (int l = 0; l < NLAYERS; l++) {
        k_spmm<<<spmm_blocks, 256>>>();
        k_transform<<<TR_GRID, 256, smem_bytes>>>(
            gc_w + l * 4096, gc_b + l * 64,
            bi_w + l * 4096, bi_b + l * 64,
            out, l);
    }
}

// round 12
// speedup vs baseline: 1.0277x; 1.0277x over previous
#include <cuda_runtime.h>
#include <math.h>

#define NUM_USERS 100000
#define NUM_ITEMS 50000
#define NROWS     150000      // NUM_USERS + NUM_ITEMS
#define NPAD      150016      // padded row count
#define EMB       64
#define NEDGES    2400000
#define NLAYERS   3
#define NEG_SLOPE 0.01f

#define SCAN_CHUNK 2048
#define NUM_CHUNKS ((NROWS + SCAN_CHUNK - 1) / SCAN_CHUNK)   // 74
#define NTILES    ((NROWS + 63) / 64)                        // 2344

typedef unsigned long long u64;

// packed fp32x2 FMA (Blackwell; ptxas never auto-fuses -> inline PTX)
#define FMA2(d, a, b, c) \
    asm("fma.rn.f32x2 %0, %1, %2, %3;" : "=l"(d) : "l"(a), "l"(b), "l"(c))
#define PACK2(d, lo, hi) \
    asm("mov.b64 %0, {%1, %2};" : "=l"(d) : "f"(lo), "f"(hi))
#define UNPACK2(lo, hi, v) \
    asm("mov.b64 {%0, %1}, %2;" : "=f"(lo), "=f"(hi) : "l"(v))

// -------- persistent device scratch (no allocations allowed) --------
__device__ __align__(16) float g_ego [NPAD * EMB];
__device__ __align__(16) float g_side[NPAD * EMB];
__device__ int  g_row_ptr[NROWS + 1];
__device__ int  g_cursor [NROWS];        // zeroed by transform(layer 0) for next replay
__device__ __align__(16) int2 g_edge[NEDGES];  // (col, val-bits)
// decoupled-lookback scan state + per-chunk done flags; zeroed by k_spmm.
__device__ volatile u64 g_scan_state[NUM_CHUNKS];
__device__ unsigned g_chunk_done[NUM_CHUNKS];

// ---------------------------------------------------------------
// Launch 0: hist (atomics into cursor) + ego init + out layer-0.
// ---------------------------------------------------------------
__global__ void k_hist_init(const int* __restrict__ rows,
                            const float* __restrict__ user_emb,
                            const float* __restrict__ item_emb,
                            float* __restrict__ out, int n_edges) {
    int idx = blockIdx.x * blockDim.x + threadIdx.x;
    if (idx < n_edges) atomicAdd(&g_cursor[rows[idx]], 1);
    if (idx >= NROWS * 16) return;
    int r = idx >> 4;
    int c4 = idx & 15;
    float4 v;
    if (r < NUM_USERS)
        v = ((const float4*)&user_emb[r * EMB])[c4];
    else
        v = ((const float4*)&item_emb[(r - NUM_USERS) * EMB])[c4];
    ((float4*)&g_ego[r * EMB])[c4] = v;
    ((float4*)&out[r * (EMB * (NLAYERS + 1))])[c4] = v;
}

// ---------------------------------------------------------------
// Launch 1: fused scan (blocks 0..73) + scatter (all blocks).
// ---------------------------------------------------------------
__global__ void __launch_bounds__(256)
k_scan_scatter(const int* __restrict__ rows,
               const int* __restrict__ cols,
               const float* __restrict__ vals, int n_edges) {
    int b = blockIdx.x, t = threadIdx.x;

    if (b < NUM_CHUNKS) {
        int base = b * SCAN_CHUNK + t * 8;
        int v[8];
        int local = 0;
#pragma unroll
        for (int i = 0; i < 8; i++) {
            int idx = base + i;
            v[i] = (idx < NROWS) ? g_cursor[idx] : 0;
            local += v[i];
        }
        __shared__ int sh[256];
        __shared__ int s_prev;
        sh[t] = local;
        __syncthreads();
        for (int d = 1; d < 256; d <<= 1) {
            int x = (t >= d) ? sh[t - d] : 0;
            __syncthreads();
            sh[t] += x;
            __syncthreads();
        }
        if (t == 255) {
            u64 agg = (u64)(unsigned)sh[255];
            if (b == 0) {
                g_scan_state[0] = (2ull << 62) | agg;
                s_prev = 0;
            } else {
                g_scan_state[b] = (1ull << 62) | agg;
                int prev = 0;
                int j = b - 1;
                while (j >= 0) {
                    u64 st;
                    do { st = g_scan_state[j]; } while ((st >> 62) == 0);
                    if ((st >> 62) == 2ull) { prev += (int)(unsigned)st; break; }
                    prev += (int)(unsigned)st;
                    j--;
                }
                g_scan_state[b] = (2ull << 62) | (u64)(unsigned)(prev + sh[255]);
                s_prev = prev;
            }
        }
        __syncthreads();

        int exc = s_prev + (t ? sh[t - 1] : 0);
#pragma unroll
        for (int i = 0; i < 8; i++) {
            int idx = base + i;
            if (idx < NROWS) {
                g_row_ptr[idx] = exc;
                g_cursor[idx]  = exc;
            }
            exc += v[i];
        }
        if (b == NUM_CHUNKS - 1 && t == 255)
            g_row_ptr[NROWS] = s_prev + sh[255];

        __syncthreads();
        __threadfence();
        if (t == 0)
            asm volatile("st.global.release.gpu.u32 [%0], %1;"
                         :: "l"(&g_chunk_done[b]), "r"(1u) : "memory");
    }

    int e = b * 256 + t;
    if (e < n_edges) {
        int r = rows[e];
        int c = r >> 11;                  // chunk index (SCAN_CHUNK = 2048)
        unsigned done;
        do {
            asm volatile("ld.global.acquire.gpu.u32 %0, [%1];"
                         : "=r"(done) : "l"(&g_chunk_done[c]) : "memory");
            if (!done) __nanosleep(64);
        } while (!done);
        int pos = atomicAdd(&g_cursor[r], 1);
        g_edge[pos] = make_int2(cols[e], __float_as_int(vals[e]));
    }
}

// ---------------------------------------------------------------
// Launch 2: SpMM side = A @ ego, warp per row; also clears scan flags.
// ---------------------------------------------------------------
__global__ void k_spmm() {
    int gid = blockIdx.x * blockDim.x + threadIdx.x;
    if (gid < NUM_CHUNKS) { g_scan_state[gid] = 0; g_chunk_done[gid] = 0; }
    int w = gid >> 5;
    int lane = threadIdx.x & 31;
    if (w >= NROWS) return;
    int s = g_row_ptr[w];
    int e = g_row_ptr[w + 1];
    float2 acc = make_float2(0.f, 0.f);
    for (int i = s; i < e; i++) {
        int2 ed = __ldg(&g_edge[i]);
        float v = __int_as_float(ed.y);
        float2 x = *(const float2*)&g_ego[ed.x * EMB + lane * 2];
        acc.x = fmaf(v, x.x, acc.x);
        acc.y = fmaf(v, x.y, acc.y);
    }
    *(float2*)&g_side[w * EMB + lane * 2] = acc;
}

// ---------------------------------------------------------------
// Launch 3 (PROFILED): transform, one 64-row tile per block (NOT persistent),
// u = ego*side folded into the k-loop (no separate staging pass).
// 256 threads: thread computes 16 cols (quarter q = t>>6) of row t&63.
// ---------------------------------------------------------------
__device__ __forceinline__ float lrelu(float a) {
    return (a > 0.f) ? a : NEG_SLOPE * a;
}

__global__ void __launch_bounds__(256)
k_transform(const float* __restrict__ W1g, const float* __restrict__ b1g,
            const float* __restrict__ W2g, const float* __restrict__ b2g,
            float* __restrict__ out, int layer) {
    extern __shared__ float sh[];
    float* W1s   = sh;                 // 4096
    float* W2s   = sh + 4096;          // 4096
    float* b1s   = sh + 8192;          // 64
    float* b2s   = sh + 8256;          // 64
    float* ssq   = sh + 8320;          // 256
    float* sideS = sh + 8576;          // 64*65 = 4160
    float* egoS  = sideS + 4160;       // 4160
    // total = 16896 floats = 67584 bytes -> 3 blocks/SM

    int t = threadIdx.x;
    int base = blockIdx.x * 64;

#pragma unroll 4
    for (int i = t; i < 1024; i += 256) {
        ((float4*)W1s)[i] = ((const float4*)W1g)[i];
        ((float4*)W2s)[i] = ((const float4*)W2g)[i];
    }
    if (t < 64) { b1s[t] = b1g[t]; b2s[t] = b2g[t]; }

    // stage side + ego for the block's 64 rows (padded stride 65)
    const float4* sg = (const float4*)&g_side[(size_t)base * EMB];
    const float4* eg = (const float4*)&g_ego [(size_t)base * EMB];
#pragma unroll 4
    for (int i = t; i < 1024; i += 256) {
        float4 sv = sg[i];
        float4 ev = eg[i];
        int rw = i >> 4;
        int c = (i & 15) * 4;
        float* ds = &sideS[rw * 65 + c];
        float* de = &egoS [rw * 65 + c];
        ds[0] = sv.x; ds[1] = sv.y; ds[2] = sv.z; ds[3] = sv.w;
        de[0] = ev.x; de[1] = ev.y; de[2] = ev.z; de[3] = ev.w;
    }
    __syncthreads();

    int row = t & 63;         // row within tile
    int q   = t >> 6;         // col quarter: cols q*16 .. q*16+15
    int r   = base + row;

    // re-zero histogram counters for next replay (cursor dead by now)
    if (layer == 0 && q == 0 && r < NROWS) g_cursor[r] = 0;

    float o[16];

    if (r < NROWS) {
        const float* srow = &sideS[row * 65];
        const float* erow = &egoS [row * 65];

        u64 acc1[8], acc2[8];
#pragma unroll
        for (int j = 0; j < 8; j++) {
            PACK2(acc1[j], b1s[q * 16 + 2 * j], b1s[q * 16 + 2 * j + 1]);
            PACK2(acc2[j], b2s[q * 16 + 2 * j], b2s[q * 16 + 2 * j + 1]);
        }
#pragma unroll 4
        for (int k = 0; k < 64; k++) {
            float s = srow[k];
            float u = s * erow[k];          // folded: u = ego*side on the fly
            u64 ss, uu;
            PACK2(ss, s, s);
            PACK2(uu, u, u);
            const u64* w1 = (const u64*)&W1s[k * 64 + q * 16];
            const u64* w2 = (const u64*)&W2s[k * 64 + q * 16];
#pragma unroll
            for (int j = 0; j < 8; j += 2) {
                ulonglong2 a = *(const ulonglong2*)&w1[j];
                FMA2(acc1[j],     ss, a.x, acc1[j]);
                FMA2(acc1[j + 1], ss, a.y, acc1[j + 1]);
                ulonglong2 b = *(const ulonglong2*)&w2[j];
                FMA2(acc2[j],     uu, b.x, acc2[j]);
                FMA2(acc2[j + 1], uu, b.y, acc2[j + 1]);
            }
        }

        float sumsq = 0.f;
#pragma unroll
        for (int j = 0; j < 8; j++) {
            float a0, a1, b0, b1;
            UNPACK2(a0, a1, acc1[j]);
            UNPACK2(b0, b1, acc2[j]);
            float o0 = lrelu(a0) + lrelu(b0);
            float o1 = lrelu(a1) + lrelu(b1);
            sumsq += o0 * o0 + o1 * o1;
            o[2 * j]     = o0;
            o[2 * j + 1] = o1;
        }
        ssq[t] = sumsq;   // t = q*64 + row

        float4* egor = (float4*)&g_ego[(size_t)r * EMB + q * 16];
#pragma unroll
        for (int j4 = 0; j4 < 4; j4++)
            egor[j4] = make_float4(o[j4 * 4], o[j4 * 4 + 1],
                                   o[j4 * 4 + 2], o[j4 * 4 + 3]);
    }
    __syncthreads();

    if (r < NROWS) {
        float total = ssq[row] + ssq[64 + row] + ssq[128 + row] + ssq[192 + row];
        float inv = 1.0f / fmaxf(sqrtf(total), 1e-12f);
        float4* orow = (float4*)&out[(size_t)r * (EMB * (NLAYERS + 1))
                                     + (layer + 1) * EMB + q * 16];
#pragma unroll
        for (int j4 = 0; j4 < 4; j4++)
            orow[j4] = make_float4(o[j4 * 4] * inv, o[j4 * 4 + 1] * inv,
                                   o[j4 * 4 + 2] * inv, o[j4 * 4 + 3] * inv);
    }
}

// ---------------------------------------------------------------
extern "C" void kernel_launch(void* const* d_in, const int* in_sizes, int n_in,
                              void* d_out, int out_size) {
    const int*   adj_rows = (const int*)  d_in[0];
    const int*   adj_cols = (const int*)  d_in[1];
    const float* adj_vals = (const float*)d_in[2];
    const float* user_emb = (const float*)d_in[3];
    const float* item_emb = (const float*)d_in[4];
    const float* gc_w     = (const float*)d_in[5];
    const float* gc_b     = (const float*)d_in[6];
    const float* bi_w     = (const float*)d_in[7];
    const float* bi_b     = (const float*)d_in[8];
    float*       out      = (float*)d_out;

    int n_edges = in_sizes[0];

    const int smem_bytes = 16896 * (int)sizeof(float); // 67584
    cudaFuncSetAttribute(k_transform, cudaFuncAttributeMaxDynamicSharedMemorySize, smem_bytes);

    // launch 0: hist + ego init + layer-0 out
    k_hist_init<<<(n_edges + 255) / 256, 256>>>(adj_rows, user_emb, item_emb,
                                                out, n_edges);
    // launch 1: fused scan + scatter
    k_scan_scatter<<<(n_edges + 255) / 256, 256>>>(adj_rows, adj_cols, adj_vals,
                                                   n_edges);

    // launches 2..7: layers (transform at index 3 -> profiled)
    int spmm_blocks = (NROWS * 32 + 255) / 256;        // warp per row
    for (int l = 0; l < NLAYERS; l++) {
        k_spmm<<<spmm_blocks, 256>>>();
        k_transform<<<NTILES, 256, smem_bytes>>>(
            gc_w + l * 4096, gc_b + l * 64,
            bi_w + l * 4096, bi_b + l * 64,
            out, l);
    }
}

// round 13
// speedup vs baseline: 1.2834x; 1.2487x over previous
#include <cuda_runtime.h>
#include <math.h>

#define NUM_USERS 100000
#define NUM_ITEMS 50000
#define NROWS     150000      // NUM_USERS + NUM_ITEMS
#define NPAD      150016      // padded row count
#define EMB       64
#define NEDGES    2400000
#define NLAYERS   3
#define NEG_SLOPE 0.01f

#define SCAN_CHUNK 2048
#define NUM_CHUNKS ((NROWS + SCAN_CHUNK - 1) / SCAN_CHUNK)   // 74
#define NTILES    ((NROWS + 63) / 64)                        // 2344

typedef unsigned long long u64;

// packed fp32x2 FMA (Blackwell; ptxas never auto-fuses -> inline PTX)
#define FMA2(d, a, b, c) \
    asm("fma.rn.f32x2 %0, %1, %2, %3;" : "=l"(d) : "l"(a), "l"(b), "l"(c))
#define PACK2(d, lo, hi) \
    asm("mov.b64 %0, {%1, %2};" : "=l"(d) : "f"(lo), "f"(hi))
#define UNPACK2(lo, hi, v) \
    asm("mov.b64 {%0, %1}, %2;" : "=f"(lo), "=f"(hi) : "l"(v))

// -------- persistent device scratch (no allocations allowed) --------
__device__ __align__(16) float g_ego [NPAD * EMB];
__device__ __align__(16) float g_side[NPAD * EMB];
__device__ int  g_row_ptr[NROWS + 1];
__device__ int  g_cursor [NROWS];        // zeroed by transform(layer 0) for next replay
__device__ __align__(16) int2 g_edge[NEDGES];  // (col, val-bits)
// decoupled-lookback scan state; zeroed by k_scatter after scan completes.
__device__ volatile u64 g_scan_state[NUM_CHUNKS];

// ---------------------------------------------------------------
// Launch 0: hist (atomics into cursor) + ego init + out layer-0.
// ---------------------------------------------------------------
__global__ void k_hist_init(const int* __restrict__ rows,
                            const float* __restrict__ user_emb,
                            const float* __restrict__ item_emb,
                            float* __restrict__ out, int n_edges) {
    int idx = blockIdx.x * blockDim.x + threadIdx.x;
    if (idx < n_edges) atomicAdd(&g_cursor[rows[idx]], 1);
    if (idx >= NROWS * 16) return;
    int r = idx >> 4;
    int c4 = idx & 15;
    float4 v;
    if (r < NUM_USERS)
        v = ((const float4*)&user_emb[r * EMB])[c4];
    else
        v = ((const float4*)&item_emb[(r - NUM_USERS) * EMB])[c4];
    ((float4*)&g_ego[r * EMB])[c4] = v;
    ((float4*)&out[r * (EMB * (NLAYERS + 1))])[c4] = v;
}

// ---------------------------------------------------------------
// Launch 1: single-kernel exclusive scan (decoupled lookback, 74 blocks).
// ---------------------------------------------------------------
__global__ void __launch_bounds__(256) k_scan() {
    int b = blockIdx.x, t = threadIdx.x;
    int base = b * SCAN_CHUNK + t * 8;
    int v[8];
    int local = 0;
#pragma unroll
    for (int i = 0; i < 8; i++) {
        int idx = base + i;
        v[i] = (idx < NROWS) ? g_cursor[idx] : 0;
        local += v[i];
    }
    __shared__ int sh[256];
    __shared__ int s_prev;
    sh[t] = local;
    __syncthreads();
    for (int d = 1; d < 256; d <<= 1) {
        int x = (t >= d) ? sh[t - d] : 0;
        __syncthreads();
        sh[t] += x;
        __syncthreads();
    }
    if (t == 255) {
        u64 agg = (u64)(unsigned)sh[255];
        if (b == 0) {
            g_scan_state[0] = (2ull << 62) | agg;
            s_prev = 0;
        } else {
            g_scan_state[b] = (1ull << 62) | agg;
            int prev = 0;
            int j = b - 1;
            while (j >= 0) {
                u64 st;
                do { st = g_scan_state[j]; } while ((st >> 62) == 0);
                if ((st >> 62) == 2ull) { prev += (int)(unsigned)st; break; }
                prev += (int)(unsigned)st;
                j--;
            }
            g_scan_state[b] = (2ull << 62) | (u64)(unsigned)(prev + sh[255]);
            s_prev = prev;
        }
    }
    __syncthreads();

    int exc = s_prev + (t ? sh[t - 1] : 0);
#pragma unroll
    for (int i = 0; i < 8; i++) {
        int idx = base + i;
        if (idx < NROWS) {
            g_row_ptr[idx] = exc;
            g_cursor[idx]  = exc;
        }
        exc += v[i];
    }
    if (b == NUM_CHUNKS - 1 && t == 255)
        g_row_ptr[NROWS] = s_prev + sh[255];
}

// ---------------------------------------------------------------
// Launch 2: scatter edges (int2) + clear scan state for next replay.
// ---------------------------------------------------------------
__global__ void k_scatter(const int* __restrict__ rows,
                          const int* __restrict__ cols,
                          const float* __restrict__ vals, int n_edges) {
    int e = blockIdx.x * blockDim.x + threadIdx.x;
    if (e < NUM_CHUNKS) g_scan_state[e] = 0;
    if (e < n_edges) {
        int r = rows[e];
        int pos = atomicAdd(&g_cursor[r], 1);
        g_edge[pos] = make_int2(cols[e], __float_as_int(vals[e]));
    }
}

// ---------------------------------------------------------------
// Launch 3 (profiled, control): SpMM side = A @ ego, warp per row.
// ---------------------------------------------------------------
__global__ void k_spmm() {
    int gid = blockIdx.x * blockDim.x + threadIdx.x;
    int w = gid >> 5;
    int lane = threadIdx.x & 31;
    if (w >= NROWS) return;
    int s = g_row_ptr[w];
    int e = g_row_ptr[w + 1];
    float2 acc = make_float2(0.f, 0.f);
    for (int i = s; i < e; i++) {
        int2 ed = __ldg(&g_edge[i]);
        float v = __int_as_float(ed.y);
        float2 x = *(const float2*)&g_ego[ed.x * EMB + lane * 2];
        acc.x = fmaf(v, x.x, acc.x);
        acc.y = fmaf(v, x.y, acc.y);
    }
    *(float2*)&g_side[w * EMB + lane * 2] = acc;
}

// ---------------------------------------------------------------
// Transform: 64-row tile/block, 256 threads, thread computes
// 2 rows x 8 cols (rows t&31 and t&31+32, col group g=t>>5).
// W reads amortized over 2 rows: 4 broadcast LDS.128 + 4 scalar LDS
// per warp*k vs 16 FMA2 -> no longer crossbar-bound. Folded u=ego*side.
// ---------------------------------------------------------------
__device__ __forceinline__ float lrelu(float a) {
    return (a > 0.f) ? a : NEG_SLOPE * a;
}

__global__ void __launch_bounds__(256)
k_transform(const float* __restrict__ W1g, const float* __restrict__ b1g,
            const float* __restrict__ W2g, const float* __restrict__ b2g,
            float* __restrict__ out, int layer) {
    extern __shared__ float sh[];
    float* W1s   = sh;                 // 4096
    float* W2s   = sh + 4096;          // 4096
    float* b1s   = sh + 8192;          // 64
    float* b2s   = sh + 8256;          // 64
    float* ssq   = sh + 8320;          // 512 (64 rows x 8 col-groups)
    float* sideS = sh + 8832;          // 64*65 = 4160
    float* egoS  = sh + 12992;         // 4160
    // total = 17152 floats = 68608 bytes -> 3 blocks/SM

    int t = threadIdx.x;
    int base = blockIdx.x * 64;

#pragma unroll 4
    for (int i = t; i < 1024; i += 256) {
        ((float4*)W1s)[i] = ((const float4*)W1g)[i];
        ((float4*)W2s)[i] = ((const float4*)W2g)[i];
    }
    if (t < 64) { b1s[t] = b1g[t]; b2s[t] = b2g[t]; }

    // stage side + ego for the block's 64 rows (padded stride 65)
    const float4* sg = (const float4*)&g_side[(size_t)base * EMB];
    const float4* eg = (const float4*)&g_ego [(size_t)base * EMB];
#pragma unroll 4
    for (int i = t; i < 1024; i += 256) {
        float4 sv = sg[i];
        float4 ev = eg[i];
        int rw = i >> 4;
        int c = (i & 15) * 4;
        float* ds = &sideS[rw * 65 + c];
        float* de = &egoS [rw * 65 + c];
        ds[0] = sv.x; ds[1] = sv.y; ds[2] = sv.z; ds[3] = sv.w;
        de[0] = ev.x; de[1] = ev.y; de[2] = ev.z; de[3] = ev.w;
    }
    __syncthreads();

    int rl0 = t & 31;          // local row 0
    int rl1 = rl0 + 32;        // local row 1
    int g   = t >> 5;          // col group: cols g*8 .. g*8+7 (warp-uniform)
    int r0  = base + rl0;
    int r1  = base + rl1;

    // re-zero histogram counters for next replay (cursor dead by now)
    if (layer == 0 && g == 0) {
        if (r0 < NROWS) g_cursor[r0] = 0;
        if (r1 < NROWS) g_cursor[r1] = 0;
    }

    const float* s0p = &sideS[rl0 * 65];
    const float* e0p = &egoS [rl0 * 65];
    const float* s1p = &sideS[rl1 * 65];
    const float* e1p = &egoS [rl1 * 65];

    u64 a1r0[4], a2r0[4], a1r1[4], a2r1[4];
#pragma unroll
    for (int j = 0; j < 4; j++) {
        u64 b1v, b2v;
        PACK2(b1v, b1s[g * 8 + 2 * j], b1s[g * 8 + 2 * j + 1]);
        PACK2(b2v, b2s[g * 8 + 2 * j], b2s[g * 8 + 2 * j + 1]);
        a1r0[j] = b1v; a1r1[j] = b1v;
        a2r0[j] = b2v; a2r1[j] = b2v;
    }

#pragma unroll 4
    for (int k = 0; k < 64; k++) {
        float s0 = s0p[k];
        float u0 = s0 * e0p[k];
        float s1 = s1p[k];
        float u1 = s1 * e1p[k];
        u64 ss0, uu0, ss1, uu1;
        PACK2(ss0, s0, s0);
        PACK2(uu0, u0, u0);
        PACK2(ss1, s1, s1);
        PACK2(uu1, u1, u1);
        ulonglong2 wa = *(const ulonglong2*)&W1s[k * 64 + g * 8];      // cols 0-3
        ulonglong2 wb = *(const ulonglong2*)&W1s[k * 64 + g * 8 + 4];  // cols 4-7
        ulonglong2 wc = *(const ulonglong2*)&W2s[k * 64 + g * 8];
        ulonglong2 wd = *(const ulonglong2*)&W2s[k * 64 + g * 8 + 4];
        FMA2(a1r0[0], ss0, wa.x, a1r0[0]);
        FMA2(a1r0[1], ss0, wa.y, a1r0[1]);
        FMA2(a1r0[2], ss0, wb.x, a1r0[2]);
        FMA2(a1r0[3], ss0, wb.y, a1r0[3]);
        FMA2(a1r1[0], ss1, wa.x, a1r1[0]);
        FMA2(a1r1[1], ss1, wa.y, a1r1[1]);
        FMA2(a1r1[2], ss1, wb.x, a1r1[2]);
        FMA2(a1r1[3], ss1, wb.y, a1r1[3]);
        FMA2(a2r0[0], uu0, wc.x, a2r0[0]);
        FMA2(a2r0[1], uu0, wc.y, a2r0[1]);
        FMA2(a2r0[2], uu0, wd.x, a2r0[2]);
        FMA2(a2r0[3], uu0, wd.y, a2r0[3]);
        FMA2(a2r1[0], uu1, wc.x, a2r1[0]);
        FMA2(a2r1[1], uu1, wc.y, a2r1[1]);
        FMA2(a2r1[2], uu1, wd.x, a2r1[2]);
        FMA2(a2r1[3], uu1, wd.y, a2r1[3]);
    }

    float o0[8], o1[8];
    float sq0 = 0.f, sq1 = 0.f;
#pragma unroll
    for (int j = 0; j < 4; j++) {
        float x0, x1, y0, y1;
        UNPACK2(x0, x1, a1r0[j]);
        UNPACK2(y0, y1, a2r0[j]);
        float p0 = lrelu(x0) + lrelu(y0);
        float p1 = lrelu(x1) + lrelu(y1);
        sq0 += p0 * p0 + p1 * p1;
        o0[2 * j] = p0; o0[2 * j + 1] = p1;
        UNPACK2(x0, x1, a1r1[j]);
        UNPACK2(y0, y1, a2r1[j]);
        p0 = lrelu(x0) + lrelu(y0);
        p1 = lrelu(x1) + lrelu(y1);
        sq1 += p0 * p0 + p1 * p1;
        o1[2 * j] = p0; o1[2 * j + 1] = p1;
    }
    ssq[rl0 * 8 + g] = sq0;
    ssq[rl1 * 8 + g] = sq1;

    if (r0 < NROWS) {
        float4* e0w = (float4*)&g_ego[(size_t)r0 * EMB + g * 8];
        e0w[0] = make_float4(o0[0], o0[1], o0[2], o0[3]);
        e0w[1] = make_float4(o0[4], o0[5], o0[6], o0[7]);
    }
    if (r1 < NROWS) {
        float4* e1w = (float4*)&g_ego[(size_t)r1 * EMB + g * 8];
        e1w[0] = make_float4(o1[0], o1[1], o1[2], o1[3]);
        e1w[1] = make_float4(o1[4], o1[5], o1[6], o1[7]);
    }
    __syncthreads();

    // row norms: sum the 8 group partials per row
    float4 q0a = *(const float4*)&ssq[rl0 * 8];
    float4 q0b = *(const float4*)&ssq[rl0 * 8 + 4];
    float4 q1a = *(const float4*)&ssq[rl1 * 8];
    float4 q1b = *(const float4*)&ssq[rl1 * 8 + 4];
    float tot0 = q0a.x + q0a.y + q0a.z + q0a.w + q0b.x + q0b.y + q0b.z + q0b.w;
    float tot1 = q1a.x + q1a.y + q1a.z + q1a.w + q1b.x + q1b.y + q1b.z + q1b.w;
    float inv0 = 1.0f / fmaxf(sqrtf(tot0), 1e-12f);
    float inv1 = 1.0f / fmaxf(sqrtf(tot1), 1e-12f);

    if (r0 < NROWS) {
        float4* ow = (float4*)&out[(size_t)r0 * (EMB * (NLAYERS + 1))
                                   + (layer + 1) * EMB + g * 8];
        ow[0] = make_float4(o0[0] * inv0, o0[1] * inv0, o0[2] * inv0, o0[3] * inv0);
        ow[1] = make_float4(o0[4] * inv0, o0[5] * inv0, o0[6] * inv0, o0[7] * inv0);
    }
    if (r1 < NROWS) {
        float4* ow = (float4*)&out[(size_t)r1 * (EMB * (NLAYERS + 1))
                                   + (layer + 1) * EMB + g * 8];
        ow[0] = make_float4(o1[0] * inv1, o1[1] * inv1, o1[2] * inv1, o1[3] * inv1);
        ow[1] = make_float4(o1[4] * inv1, o1[5] * inv1, o1[6] * inv1, o1[7] * inv1);
    }
}

// ---------------------------------------------------------------
extern "C" void kernel_launch(void* const* d_in, const int* in_sizes, int n_in,
                              void* d_out, int out_size) {
    const int*   adj_rows = (const int*)  d_in[0];
    const int*   adj_cols = (const int*)  d_in[1];
    const float* adj_vals = (const float*)d_in[2];
    const float* user_emb = (const float*)d_in[3];
    const float* item_emb = (const float*)d_in[4];
    const float* gc_w     = (const float*)d_in[5];
    const float* gc_b     = (const float*)d_in[6];
    const float* bi_w     = (const float*)d_in[7];
    const float* bi_b     = (const float*)d_in[8];
    float*       out      = (float*)d_out;

    int n_edges = in_sizes[0];

    const int smem_bytes = 17152 * (int)sizeof(float); // 68608
    cudaFuncSetAttribute(k_transform, cudaFuncAttributeMaxDynamicSharedMemorySize, smem_bytes);

    // launch 0: hist + ego init + layer-0 out
    k_hist_init<<<(n_edges + 255) / 256, 256>>>(adj_rows, user_emb, item_emb,
                                                out, n_edges);
    // launch 1: scan
    k_scan<<<NUM_CHUNKS, 256>>>();
    // launch 2: scatter (+ scan-state cleanup)
    k_scatter<<<(n_edges + 255) / 256, 256>>>(adj_rows, adj_cols, adj_vals, n_edges);

    // launches 3..8: layers (spmm at index 3 -> profiled control)
    int spmm_blocks = (NROWS * 32 + 255) / 256;        // warp per row
    for (int l = 0; l < NLAYERS; l++) {
        k_spmm<<<spmm_blocks, 256>>>();
        k_transform<<<NTILES, 256, smem_bytes>>>(
            gc_w + l * 4096, gc_b + l * 64,
            bi_w + l * 4096, bi_b + l * 64,
            out, l);
    }
}